// round 7
// baseline (speedup 1.0000x reference)
#include <cuda_runtime.h>

#define E_TOTAL 1000000
#define FX      32
#define D0      96
#define HID     64
#define OUTC    32
#define KL2     160
#define THREADS 256
#define TILE_E  256
#define ESTR    260            // TILE_E + 4: row bases stay 16B-aligned, banks shift by 4/row
#define NTILES  ((E_TOTAL + TILE_E - 1) / TILE_E)
#define GRID    152
#define LN_EPS  1e-5f

typedef unsigned long long u64;

// ---- packed f32x2 helpers (sm_103a FFMA2 path, PTX-only per SASS_QUICKREF) ----
__device__ __forceinline__ u64 pack2(float x, float y) {
    u64 r;
    asm("mov.b64 %0, {%1, %2};" : "=l"(r) : "r"(__float_as_uint(x)), "r"(__float_as_uint(y)));
    return r;
}
__device__ __forceinline__ u64 dup2(float x) {
    u64 r;
    unsigned u = __float_as_uint(x);
    asm("mov.b64 %0, {%1, %2};" : "=l"(r) : "r"(u), "r"(u));
    return r;
}
__device__ __forceinline__ void fma2(u64 &d, u64 a, u64 b) {
    asm("fma.rn.f32x2 %0, %1, %2, %3;" : "=l"(d) : "l"(a), "l"(b), "l"(d));
}
__device__ __forceinline__ void unpack2(u64 v, float &x, float &y) {
    unsigned lo, hi;
    asm("mov.b64 {%0, %1}, %2;" : "=r"(lo), "=r"(hi) : "l"(v));
    x = __uint_as_float(lo);
    y = __uint_as_float(hi);
}

__device__ __forceinline__ void cp4(float* dst, const float* src, int n, int tid) {
    float4* d4 = (float4*)dst;
    const float4* s4 = (const float4*)src;
    for (int i = tid; i < (n >> 2); i += THREADS) d4[i] = s4[i];
}

// relu -> LayerNorm(64) over 8 edges x 8 cols -> transposed store into xs
// LN constants read via __ldg (uniform, L1-resident).
__device__ __forceinline__ void relu_ln_store8(
    u64 acc[8][4], const float* __restrict__ bias, const float* __restrict__ gamma,
    const float* __restrict__ beta, float* __restrict__ xs,
    int rowBase, int e0, int c0)
{
    float v[8][8];
#pragma unroll
    for (int e = 0; e < 8; e++) {
        unpack2(acc[e][0], v[e][0], v[e][1]);
        unpack2(acc[e][1], v[e][2], v[e][3]);
        unpack2(acc[e][2], v[e][4], v[e][5]);
        unpack2(acc[e][3], v[e][6], v[e][7]);
    }
    float4 bA = __ldg((const float4*)&bias[c0]);
    float4 bB = __ldg((const float4*)&bias[c0 + 4]);
    float bb[8] = {bA.x, bA.y, bA.z, bA.w, bB.x, bB.y, bB.z, bB.w};
    float s[8], q[8];
#pragma unroll
    for (int e = 0; e < 8; e++) {
        float se = 0.f, qe = 0.f;
#pragma unroll
        for (int c = 0; c < 8; c++) {
            float t = fmaxf(v[e][c] + bb[c], 0.f);
            v[e][c] = t;
            se += t;
            qe += t * t;
        }
        s[e] = se; q[e] = qe;
    }
    // 8 threads (lanes with equal lane>>3) share one edge's 64 channels
#pragma unroll
    for (int m = 1; m < 8; m <<= 1) {
#pragma unroll
        for (int e = 0; e < 8; e++) {
            s[e] += __shfl_xor_sync(0xffffffffu, s[e], m);
            q[e] += __shfl_xor_sync(0xffffffffu, q[e], m);
        }
    }
    float4 gA = __ldg((const float4*)&gamma[c0]);
    float4 gB = __ldg((const float4*)&gamma[c0 + 4]);
    float4 tA = __ldg((const float4*)&beta[c0]);
    float4 tB = __ldg((const float4*)&beta[c0 + 4]);
    float gm[8] = {gA.x, gA.y, gA.z, gA.w, gB.x, gB.y, gB.z, gB.w};
    float bt[8] = {tA.x, tA.y, tA.z, tA.w, tB.x, tB.y, tB.z, tB.w};
#pragma unroll
    for (int e = 0; e < 8; e++) {
        float mean = s[e] * (1.f / 64.f);
        float var  = q[e] * (1.f / 64.f) - mean * mean;
        float rstd = rsqrtf(var + LN_EPS);
#pragma unroll
        for (int c = 0; c < 8; c++)
            v[e][c] = (v[e][c] - mean) * rstd * gm[c] + bt[c];
    }
#pragma unroll
    for (int c = 0; c < 8; c++) {
        float* row = &xs[(rowBase + c0 + c) * ESTR];
        *(float4*)&row[e0]     = make_float4(v[0][c], v[1][c], v[2][c], v[3][c]);
        *(float4*)&row[e0 + 4] = make_float4(v[4][c], v[5][c], v[6][c], v[7][c]);
    }
}

__global__ __launch_bounds__(THREADS, 1)
void EdgeModel_48636209660177_kernel(
    const float* __restrict__ src, const float* __restrict__ dst,
    const float* __restrict__ ea,
    const float* __restrict__ W1, const float* __restrict__ b1,
    const float* __restrict__ g1, const float* __restrict__ be1,
    const float* __restrict__ W2, const float* __restrict__ b2,
    const float* __restrict__ g2, const float* __restrict__ be2,
    const float* __restrict__ W3, const float* __restrict__ b3,
    float* __restrict__ out)
{
    extern __shared__ float sm[];
    float* sW1 = sm;                  // 96*64  = 6144
    float* sW2 = sW1 + 6144;          // 160*64 = 10240
    float* xs  = sW2 + 10240;         // 160 rows * ESTR

    const int tid = threadIdx.x;
    cp4(sW1, W1, 6144, tid);
    cp4(sW2, W2, 10240, tid);

    const int eg = tid >> 3;    // 0..31 -> 8 edges each
    const int cg = tid & 7;     // 0..7  -> 8 cols each (layers 1/2), 4 cols (layer 3)
    const int e0 = eg * 8;
    const int c0 = cg * 8;

    for (int tile = blockIdx.x; tile < NTILES; tile += gridDim.x) {
        const int ebase = tile * TILE_E;
        __syncthreads();   // protect xs from previous tile's layer-3 reads

        // ---- stage x0 = concat(src,dest,edge_attr) transposed into rows 64..159 ----
#pragma unroll
        for (int t = 0; t < 3; t++) {
            const float* g = (t == 0) ? src : (t == 1) ? dst : ea;
            const int R = 64 + t * 32;
            for (int i = tid; i < TILE_E * 8; i += THREADS) {
                int e = i >> 3, c4 = (i & 7) * 4;
                float4 v = make_float4(0.f, 0.f, 0.f, 0.f);
                if (ebase + e < E_TOTAL)
                    v = *(const float4*)&g[(size_t)(ebase + e) * FX + c4];
                xs[(R + c4 + 0) * ESTR + e] = v.x;
                xs[(R + c4 + 1) * ESTR + e] = v.y;
                xs[(R + c4 + 2) * ESTR + e] = v.z;
                xs[(R + c4 + 3) * ESTR + e] = v.w;
            }
        }
        __syncthreads();

        // ---- layer 1: h1 = LN(relu(x0 @ W1 + b1)) -> rows 0..63 ----
        {
            u64 acc[8][4];
#pragma unroll
            for (int e = 0; e < 8; e++)
#pragma unroll
                for (int j = 0; j < 4; j++) acc[e][j] = 0ull;
#pragma unroll 2
            for (int k = 0; k < D0; k++) {
                const float* xr = &xs[(64 + k) * ESTR + e0];
                float4 xv0 = *(const float4*)&xr[0];
                float4 xv1 = *(const float4*)&xr[4];
                const float* wr = &sW1[k * HID + c0];
                float4 wv0 = *(const float4*)&wr[0];
                float4 wv1 = *(const float4*)&wr[4];
                u64 w0 = pack2(wv0.x, wv0.y), w1 = pack2(wv0.z, wv0.w);
                u64 w2 = pack2(wv1.x, wv1.y), w3 = pack2(wv1.z, wv1.w);
                float xa[8] = {xv0.x, xv0.y, xv0.z, xv0.w, xv1.x, xv1.y, xv1.z, xv1.w};
#pragma unroll
                for (int e = 0; e < 8; e++) {
                    u64 a = dup2(xa[e]);
                    fma2(acc[e][0], a, w0); fma2(acc[e][1], a, w1);
                    fma2(acc[e][2], a, w2); fma2(acc[e][3], a, w3);
                }
            }
            relu_ln_store8(acc, b1, g1, be1, xs, 0, e0, c0);
        }
        __syncthreads();

        // ---- layer 2: h2 = LN(relu(concat(h1,x0) @ W2 + b2)) -> rows 64..127 ----
        {
            u64 acc[8][4];
#pragma unroll
            for (int e = 0; e < 8; e++)
#pragma unroll
                for (int j = 0; j < 4; j++) acc[e][j] = 0ull;
#pragma unroll 2
            for (int k = 0; k < KL2; k++) {
                const float* xr = &xs[k * ESTR + e0];
                float4 xv0 = *(const float4*)&xr[0];
                float4 xv1 = *(const float4*)&xr[4];
                const float* wr = &sW2[k * HID + c0];
                float4 wv0 = *(const float4*)&wr[0];
                float4 wv1 = *(const float4*)&wr[4];
                u64 w0 = pack2(wv0.x, wv0.y), w1 = pack2(wv0.z, wv0.w);
                u64 w2 = pack2(wv1.x, wv1.y), w3 = pack2(wv1.z, wv1.w);
                float xa[8] = {xv0.x, xv0.y, xv0.z, xv0.w, xv1.x, xv1.y, xv1.z, xv1.w};
#pragma unroll
                for (int e = 0; e < 8; e++) {
                    u64 a = dup2(xa[e]);
                    fma2(acc[e][0], a, w0); fma2(acc[e][1], a, w1);
                    fma2(acc[e][2], a, w2); fma2(acc[e][3], a, w3);
                }
            }
            __syncthreads();   // all reads of rows 0..159 done before overwriting 64..127
            relu_ln_store8(acc, b2, g2, be2, xs, 64, e0, c0);
        }
        __syncthreads();

        // ---- layer 3: out = h2 @ W3 + b3  (W3 via __ldg, L1-resident) ----
        {
            const int c0b = cg * 4;
            u64 acc3[8][2];
#pragma unroll
            for (int e = 0; e < 8; e++) { acc3[e][0] = 0ull; acc3[e][1] = 0ull; }
#pragma unroll 2
            for (int k = 0; k < HID; k++) {
                const float* xr = &xs[(64 + k) * ESTR + e0];
                float4 xv0 = *(const float4*)&xr[0];
                float4 xv1 = *(const float4*)&xr[4];
                float4 wv = __ldg((const float4*)&W3[k * OUTC + c0b]);
                u64 w0 = pack2(wv.x, wv.y), w1 = pack2(wv.z, wv.w);
                float xa[8] = {xv0.x, xv0.y, xv0.z, xv0.w, xv1.x, xv1.y, xv1.z, xv1.w};
#pragma unroll
                for (int e = 0; e < 8; e++) {
                    u64 a = dup2(xa[e]);
                    fma2(acc3[e][0], a, w0); fma2(acc3[e][1], a, w1);
                }
            }
            float4 bv = __ldg((const float4*)&b3[c0b]);
#pragma unroll
            for (int e = 0; e < 8; e++) {
                int ge = ebase + e0 + e;
                if (ge < E_TOTAL) {
                    float x0f, y0f, x1f, y1f;
                    unpack2(acc3[e][0], x0f, y0f);
                    unpack2(acc3[e][1], x1f, y1f);
                    *(float4*)&out[(size_t)ge * OUTC + c0b] =
                        make_float4(x0f + bv.x, y0f + bv.y, x1f + bv.z, y1f + bv.w);
                }
            }
        }
    }
}

#define SMEM_BYTES ((6144 + 10240 + 160 * ESTR) * (int)sizeof(float))

extern "C" void kernel_launch(void* const* d_in, const int* in_sizes, int n_in,
                              void* d_out, int out_size) {
    (void)in_sizes; (void)n_in; (void)out_size;
    const float* src = (const float*)d_in[0];
    const float* dst = (const float*)d_in[1];
    const float* ea  = (const float*)d_in[2];
    const float* W1  = (const float*)d_in[3];
    const float* b1  = (const float*)d_in[4];
    const float* g1  = (const float*)d_in[5];
    const float* be1 = (const float*)d_in[6];
    const float* W2  = (const float*)d_in[7];
    const float* b2  = (const float*)d_in[8];
    const float* g2  = (const float*)d_in[9];
    const float* be2 = (const float*)d_in[10];
    const float* W3  = (const float*)d_in[11];
    const float* b3  = (const float*)d_in[12];
    float* out = (float*)d_out;

    cudaFuncSetAttribute(EdgeModel_48636209660177_kernel,
                         cudaFuncAttributeMaxDynamicSharedMemorySize, SMEM_BYTES);
    EdgeModel_48636209660177_kernel<<<GRID, THREADS, SMEM_BYTES>>>(
        src, dst, ea, W1, b1, g1, be1, W2, b2, g2, be2, W3, b3, out);
}

// round 8
// speedup vs baseline: 1.0055x; 1.0055x over previous
#include <cuda_runtime.h>

#define E_TOTAL 1000000
#define THREADS 512
#define TILE_E  192
#define RS      172          // xs row stride (words): 172 % 32 = 12 -> conflict-free x loads; 16B aligned
#define S1      100          // W1T row stride (96+4):  100 % 32 = 4 -> conflict-free across 8 cg lanes
#define S2      164          // W2T row stride (160+4): 164 % 32 = 4
#define S3      68           // W3T row stride (64+4):  68 % 32 = 4
#define NTILES  ((E_TOTAL + TILE_E - 1) / TILE_E)
#define GRID    152
#define LN_EPS  1e-5f

typedef unsigned long long u64;

__device__ __forceinline__ void fma2(u64 &d, u64 a, u64 b) {
    asm("fma.rn.f32x2 %0, %1, %2, %3;" : "=l"(d) : "l"(a), "l"(b), "l"(d));
}
__device__ __forceinline__ float hsum2(u64 v) {
    unsigned lo, hi;
    asm("mov.b64 {%0, %1}, %2;" : "=r"(lo), "=r"(hi) : "l"(v));
    return __uint_as_float(lo) + __uint_as_float(hi);
}

// GEMM block: 3 edges x 8 cols per thread, dot along k (both operands k-packed).
// xr[e] -> xs row pointers (already offset to k=0 of this layer's input)
// wt    -> transposed weights base + cg row offset; col j lives at row stride 8*WS
template<int KC, int WS>
__device__ __forceinline__ void mma3x8(
    const float* __restrict__ xr0, const float* __restrict__ xr1,
    const float* __restrict__ xr2, const float* __restrict__ wt,
    u64 acc[3][8])
{
#pragma unroll
    for (int e = 0; e < 3; e++)
#pragma unroll
        for (int j = 0; j < 8; j++) acc[e][j] = 0ull;
#pragma unroll 2
    for (int k = 0; k < KC; k += 4) {
        ulonglong2 xa = *(const ulonglong2*)(xr0 + k);
        ulonglong2 xb = *(const ulonglong2*)(xr1 + k);
        ulonglong2 xc = *(const ulonglong2*)(xr2 + k);
#pragma unroll
        for (int j = 0; j < 8; j++) {
            ulonglong2 w = *(const ulonglong2*)(wt + j * 8 * WS + k);
            fma2(acc[0][j], xa.x, w.x); fma2(acc[0][j], xa.y, w.y);
            fma2(acc[1][j], xb.x, w.x); fma2(acc[1][j], xb.y, w.y);
            fma2(acc[2][j], xc.x, w.x); fma2(acc[2][j], xc.y, w.y);
        }
    }
}

// relu -> LayerNorm(64) -> store h into xs[e][cg+8j] (cols 0..63)
__device__ __forceinline__ void relu_ln_store(
    u64 acc[3][8], const float* __restrict__ bias, const float* __restrict__ gamma,
    const float* __restrict__ beta, float* __restrict__ xs, int e0, int cg)
{
    float v[3][8];
    float s[3], q[3];
#pragma unroll
    for (int e = 0; e < 3; e++) {
        float se = 0.f, qe = 0.f;
#pragma unroll
        for (int j = 0; j < 8; j++) {
            float t = hsum2(acc[e][j]) + __ldg(&bias[cg + 8 * j]);
            t = fmaxf(t, 0.f);
            v[e][j] = t;
            se += t;
            qe += t * t;
        }
        s[e] = se; q[e] = qe;
    }
    // 8 threads (same lane>>3) share one edge's 64 channels
#pragma unroll
    for (int m = 1; m < 8; m <<= 1) {
#pragma unroll
        for (int e = 0; e < 3; e++) {
            s[e] += __shfl_xor_sync(0xffffffffu, s[e], m);
            q[e] += __shfl_xor_sync(0xffffffffu, q[e], m);
        }
    }
#pragma unroll
    for (int e = 0; e < 3; e++) {
        float mean = s[e] * (1.f / 64.f);
        float var  = q[e] * (1.f / 64.f) - mean * mean;
        float rstd = rsqrtf(var + LN_EPS);
        float* row = &xs[(e0 + e) * RS];
#pragma unroll
        for (int j = 0; j < 8; j++) {
            int c = cg + 8 * j;
            row[c] = (v[e][j] - mean) * rstd * __ldg(&gamma[c]) + __ldg(&beta[c]);
        }
    }
}

__global__ __launch_bounds__(THREADS, 1)
void EdgeModel_48636209660177_kernel(
    const float* __restrict__ src, const float* __restrict__ dst,
    const float* __restrict__ ea,
    const float* __restrict__ W1, const float* __restrict__ b1,
    const float* __restrict__ g1, const float* __restrict__ be1,
    const float* __restrict__ W2, const float* __restrict__ b2,
    const float* __restrict__ g2, const float* __restrict__ be2,
    const float* __restrict__ W3, const float* __restrict__ b3,
    float* __restrict__ out)
{
    extern __shared__ float sm[];
    float* sW1T = sm;                    // 64 rows * S1  = 6400
    float* sW2T = sW1T + 64 * S1;        // 64 rows * S2  = 10496
    float* sW3T = sW2T + 64 * S2;        // 32 rows * S3  = 2176
    float* xs   = sW3T + 32 * S3;        // 192 rows * RS = 33024
    // xs cols: [0..63] = h (layer output), [64..159] = x0 concat

    const int tid = threadIdx.x;

    // ---- one-time: transpose weights into smem (coalesced global reads) ----
    for (int i = tid; i < 96 * 64; i += THREADS) {
        int k = i >> 6, c = i & 63;
        sW1T[c * S1 + k] = W1[i];
    }
    for (int i = tid; i < 160 * 64; i += THREADS) {
        int k = i >> 6, c = i & 63;
        sW2T[c * S2 + k] = W2[i];
    }
    for (int i = tid; i < 64 * 32; i += THREADS) {
        int k = i >> 5, c = i & 31;
        sW3T[c * S3 + k] = W3[i];
    }

    const int cg = tid & 7;      // col group: owns cols {cg + 8j}
    const int eg = tid >> 3;     // 0..63 edge groups, 3 edges each
    const int e0 = eg * 3;
    const float* w1t = sW1T + cg * S1;
    const float* w2t = sW2T + cg * S2;
    const float* w3t = sW3T + cg * S3;

    for (int tile = blockIdx.x; tile < NTILES; tile += gridDim.x) {
        const int ebase = tile * TILE_E;
        __syncthreads();   // prev tile's out-copy reads of xs done

        // ---- stage x0 = concat(src,dest,edge_attr) row-major into cols 64..159 ----
        {
            const float* gsrc[3] = {src, dst, ea};
#pragma unroll
            for (int t = 0; t < 3; t++) {
                const float* g = gsrc[t];
                for (int i = tid; i < TILE_E * 8; i += THREADS) {
                    int e = i >> 3, seg = (i & 7) * 4;
                    float4 v = make_float4(0.f, 0.f, 0.f, 0.f);
                    if (ebase + e < E_TOTAL)
                        v = *(const float4*)&g[(size_t)(ebase + e) * 32 + seg];
                    *(float4*)&xs[e * RS + 64 + t * 32 + seg] = v;
                }
            }
        }
        __syncthreads();

        u64 acc[3][8];

        // ---- layer 1: h1 = LN(relu(x0 @ W1 + b1)) -> cols 0..63 ----
        mma3x8<96, S1>(&xs[(e0 + 0) * RS + 64], &xs[(e0 + 1) * RS + 64],
                       &xs[(e0 + 2) * RS + 64], w1t, acc);
        relu_ln_store(acc, b1, g1, be1, xs, e0, cg);
        __syncthreads();

        // ---- layer 2: h2 = LN(relu([h1,x0] @ W2 + b2)) -> cols 0..63 ----
        mma3x8<160, S2>(&xs[(e0 + 0) * RS], &xs[(e0 + 1) * RS],
                        &xs[(e0 + 2) * RS], w2t, acc);
        __syncthreads();   // all layer-2 reads of cols 0..159 done before overwrite
        relu_ln_store(acc, b2, g2, be2, xs, e0, cg);
        __syncthreads();

        // ---- layer 3: out = h2 @ W3 + b3 -> staged into cols 64..95 ----
        {
            u64 acc3[3][4];
#pragma unroll
            for (int e = 0; e < 3; e++)
#pragma unroll
                for (int j = 0; j < 4; j++) acc3[e][j] = 0ull;
#pragma unroll 2
            for (int k = 0; k < 64; k += 4) {
                ulonglong2 xa = *(const ulonglong2*)(&xs[(e0 + 0) * RS] + k);
                ulonglong2 xb = *(const ulonglong2*)(&xs[(e0 + 1) * RS] + k);
                ulonglong2 xc = *(const ulonglong2*)(&xs[(e0 + 2) * RS] + k);
#pragma unroll
                for (int j = 0; j < 4; j++) {
                    ulonglong2 w = *(const ulonglong2*)(w3t + j * 8 * S3 + k);
                    fma2(acc3[0][j], xa.x, w.x); fma2(acc3[0][j], xa.y, w.y);
                    fma2(acc3[1][j], xb.x, w.x); fma2(acc3[1][j], xb.y, w.y);
                    fma2(acc3[2][j], xc.x, w.x); fma2(acc3[2][j], xc.y, w.y);
                }
            }
#pragma unroll
            for (int e = 0; e < 3; e++) {
                float* row = &xs[(e0 + e) * RS + 64];
#pragma unroll
                for (int j = 0; j < 4; j++) {
                    int c = cg + 8 * j;
                    row[c] = hsum2(acc3[e][j]) + __ldg(&b3[c]);
                }
            }
        }
        __syncthreads();

        // ---- coalesced copy of staged output (cols 64..95) to global ----
        for (int i = tid; i < TILE_E * 8; i += THREADS) {
            int e = i >> 3, seg = (i & 7) * 4;
            int ge = ebase + e;
            if (ge < E_TOTAL)
                *(float4*)&out[(size_t)ge * 32 + seg] = *(const float4*)&xs[e * RS + 64 + seg];
        }
    }
}

#define SMEM_BYTES ((64 * S1 + 64 * S2 + 32 * S3 + TILE_E * RS) * (int)sizeof(float))

extern "C" void kernel_launch(void* const* d_in, const int* in_sizes, int n_in,
                              void* d_out, int out_size) {
    (void)in_sizes; (void)n_in; (void)out_size;
    const float* src = (const float*)d_in[0];
    const float* dst = (const float*)d_in[1];
    const float* ea  = (const float*)d_in[2];
    const float* W1  = (const float*)d_in[3];
    const float* b1  = (const float*)d_in[4];
    const float* g1  = (const float*)d_in[5];
    const float* be1 = (const float*)d_in[6];
    const float* W2  = (const float*)d_in[7];
    const float* b2  = (const float*)d_in[8];
    const float* g2  = (const float*)d_in[9];
    const float* be2 = (const float*)d_in[10];
    const float* W3  = (const float*)d_in[11];
    const float* b3  = (const float*)d_in[12];
    float* out = (float*)d_out;

    cudaFuncSetAttribute(EdgeModel_48636209660177_kernel,
                         cudaFuncAttributeMaxDynamicSharedMemorySize, SMEM_BYTES);
    EdgeModel_48636209660177_kernel<<<GRID, THREADS, SMEM_BYTES>>>(
        src, dst, ea, W1, b1, g1, be1, W2, b2, g2, be2, W3, b3, out);
}

// round 10
// speedup vs baseline: 2.0570x; 2.0456x over previous
#include <cuda_runtime.h>
#include <cuda_bf16.h>

#define E_TOTAL 1000000
#define THREADS 256
#define TILE_E  128
#define NTILES  ((E_TOTAL + TILE_E - 1) / TILE_E)
#define GRID    152
#define LN_EPS  1e-5f

typedef unsigned int u32;

// ---- SMEM byte offsets (all 16B aligned) ----
// weights transposed [n][k] bf16, padded strides (halves): W1 104, W2 168, W3 72
#define W1H 0
#define W1L 13312
#define W2H 26624
#define W2L 48128
#define W3H 69632
#define W3L 74240
#define X0H 78848      // x0 [128][104] bf16
#define X0L 105472
#define H1H 132096     // h  [128][72] bf16
#define H1L 150528
#define H2H 168960
#define H2L 187392
#define LNP 205824     // 416 floats: b1,g1,be1,b2,g2,be2 (64 each), b3 (32)
#define SMEM_TOTAL (205824 + 416*4)

__device__ __forceinline__ u32 smem_u32(const void* p) {
    u32 a;
    asm("{ .reg .u64 t; cvta.to.shared.u64 t, %1; cvt.u32.u64 %0, t; }" : "=r"(a) : "l"(p));
    return a;
}
__device__ __forceinline__ void ldmx4(u32 r[4], u32 addr) {
    asm volatile("ldmatrix.sync.aligned.m8n8.x4.shared.b16 {%0,%1,%2,%3}, [%4];"
                 : "=r"(r[0]), "=r"(r[1]), "=r"(r[2]), "=r"(r[3]) : "r"(addr));
}
__device__ __forceinline__ void ldmx2(u32 &r0, u32 &r1, u32 addr) {
    asm volatile("ldmatrix.sync.aligned.m8n8.x2.shared.b16 {%0,%1}, [%2];"
                 : "=r"(r0), "=r"(r1) : "r"(addr));
}
__device__ __forceinline__ void mmabf(float c[4], const u32 a[4], u32 b0, u32 b1) {
    asm volatile(
        "mma.sync.aligned.m16n8k16.row.col.f32.bf16.bf16.f32 "
        "{%0,%1,%2,%3}, {%4,%5,%6,%7}, {%8,%9}, {%0,%1,%2,%3};"
        : "+f"(c[0]), "+f"(c[1]), "+f"(c[2]), "+f"(c[3])
        : "r"(a[0]), "r"(a[1]), "r"(a[2]), "r"(a[3]), "r"(b0), "r"(b1));
}
__device__ __forceinline__ void bfsplit(float x, unsigned short &h, unsigned short &l) {
    __nv_bfloat16 hb = __float2bfloat16(x);
    float rem = x - __bfloat162float(hb);
    __nv_bfloat16 lb = __float2bfloat16(rem);
    h = __bfloat16_as_ushort(hb);
    l = __bfloat16_as_ushort(lb);
}
__device__ __forceinline__ u32 pk(unsigned short a, unsigned short b) {
    return (u32)a | ((u32)b << 16);
}

// relu -> LN(64) -> bf16 hi/lo -> h arrays (stride 72 halves). Own warp rows only.
__device__ __forceinline__ void ln_epilogue(
    float c[8][4], const float* __restrict__ lnb, const float* __restrict__ lng,
    const float* __restrict__ lnbe, char* smem, int hH, int hL, int e0, int lane)
{
    const int tg = lane & 3, gid = lane >> 2;
    float vA[16], vB[16], sA = 0.f, qA = 0.f, sB = 0.f, qB = 0.f;
#pragma unroll
    for (int j = 0; j < 8; j++) {
        int col = 8 * j + 2 * tg;
        float b0 = lnb[col], b1 = lnb[col + 1];
        float a0 = fmaxf(c[j][0] + b0, 0.f), a1 = fmaxf(c[j][1] + b1, 0.f);
        float d0 = fmaxf(c[j][2] + b0, 0.f), d1 = fmaxf(c[j][3] + b1, 0.f);
        vA[2 * j] = a0; vA[2 * j + 1] = a1;
        vB[2 * j] = d0; vB[2 * j + 1] = d1;
        sA += a0 + a1; qA += a0 * a0 + a1 * a1;
        sB += d0 + d1; qB += d0 * d0 + d1 * d1;
    }
#pragma unroll
    for (int m = 1; m < 4; m <<= 1) {
        sA += __shfl_xor_sync(0xffffffffu, sA, m);
        qA += __shfl_xor_sync(0xffffffffu, qA, m);
        sB += __shfl_xor_sync(0xffffffffu, sB, m);
        qB += __shfl_xor_sync(0xffffffffu, qB, m);
    }
    float mA = sA * (1.f / 64.f), mB = sB * (1.f / 64.f);
    float rA = rsqrtf(qA * (1.f / 64.f) - mA * mA + LN_EPS);
    float rB = rsqrtf(qB * (1.f / 64.f) - mB * mB + LN_EPS);
    const int rowA = e0 + gid, rowB = rowA + 8;
#pragma unroll
    for (int j = 0; j < 8; j++) {
        int col = 8 * j + 2 * tg;
        float g0 = lng[col], g1v = lng[col + 1];
        float p0 = lnbe[col], p1 = lnbe[col + 1];
        float yA0 = (vA[2 * j] - mA) * rA * g0 + p0;
        float yA1 = (vA[2 * j + 1] - mA) * rA * g1v + p1;
        float yB0 = (vB[2 * j] - mB) * rB * g0 + p0;
        float yB1 = (vB[2 * j + 1] - mB) * rB * g1v + p1;
        unsigned short h0, l0, h1, l1;
        bfsplit(yA0, h0, l0); bfsplit(yA1, h1, l1);
        *(u32*)(smem + hH + (rowA * 72 + col) * 2) = pk(h0, h1);
        *(u32*)(smem + hL + (rowA * 72 + col) * 2) = pk(l0, l1);
        bfsplit(yB0, h0, l0); bfsplit(yB1, h1, l1);
        *(u32*)(smem + hH + (rowB * 72 + col) * 2) = pk(h0, h1);
        *(u32*)(smem + hL + (rowB * 72 + col) * 2) = pk(l0, l1);
    }
}

__global__ __launch_bounds__(THREADS, 1)
void EdgeModel_48636209660177_kernel(
    const float* __restrict__ src, const float* __restrict__ dst,
    const float* __restrict__ ea,
    const float* __restrict__ W1, const float* __restrict__ b1,
    const float* __restrict__ g1, const float* __restrict__ be1,
    const float* __restrict__ W2, const float* __restrict__ b2,
    const float* __restrict__ g2, const float* __restrict__ be2,
    const float* __restrict__ W3, const float* __restrict__ b3,
    float* __restrict__ out)
{
    extern __shared__ char smem[];
    const u32 smb = smem_u32(smem);
    const int tid = threadIdx.x, lane = tid & 31, warp = tid >> 5;
    float* lnp = (float*)(smem + LNP);

    // ---- one-time: weights -> transposed bf16 hi/lo; LN params -> smem ----
    for (int i = tid; i < 96 * 64; i += THREADS) {
        int k = i >> 6, n = i & 63;
        unsigned short h, l; bfsplit(__ldg(&W1[i]), h, l);
        int off = (n * 104 + k) * 2;
        *(unsigned short*)(smem + W1H + off) = h;
        *(unsigned short*)(smem + W1L + off) = l;
    }
    for (int i = tid; i < 160 * 64; i += THREADS) {
        int k = i >> 6, n = i & 63;
        unsigned short h, l; bfsplit(__ldg(&W2[i]), h, l);
        int off = (n * 168 + k) * 2;
        *(unsigned short*)(smem + W2H + off) = h;
        *(unsigned short*)(smem + W2L + off) = l;
    }
    for (int i = tid; i < 64 * 32; i += THREADS) {
        int k = i >> 5, n = i & 31;
        unsigned short h, l; bfsplit(__ldg(&W3[i]), h, l);
        int off = (n * 72 + k) * 2;
        *(unsigned short*)(smem + W3H + off) = h;
        *(unsigned short*)(smem + W3L + off) = l;
    }
    for (int i = tid; i < 64; i += THREADS) {
        lnp[i] = b1[i]; lnp[64 + i] = g1[i]; lnp[128 + i] = be1[i];
        lnp[192 + i] = b2[i]; lnp[256 + i] = g2[i]; lnp[320 + i] = be2[i];
    }
    for (int i = tid; i < 32; i += THREADS) lnp[384 + i] = b3[i];
    __syncthreads();

    const int e0 = warp * 16;               // this warp's 16 edge rows (fixed)
    const int tg = lane & 3, gid = lane >> 2;
    // ldmatrix lane-address components
    const int arow = lane & 15, asel = lane >> 4;      // A: row, k-half
    const int bn = lane & 7, bsel = (lane >> 3) & 1;   // B: n-row, k-half

    for (int tile = blockIdx.x; tile < NTILES; tile += GRID) {
        const int eb = tile * TILE_E;

        // ---- stage own 16 edges of x0 (bf16 hi/lo, [e][k] stride 104) ----
        for (int i = lane; i < 16 * 24; i += 32) {
            int el = i / 24, s = i % 24;
            int ge = eb + e0 + el;
            const float* g = (s < 8) ? src : (s < 16) ? dst : ea;
            int seg = s & 7;
            float4 v = make_float4(0.f, 0.f, 0.f, 0.f);
            if (ge < E_TOTAL) v = *(const float4*)(g + (size_t)ge * 32 + seg * 4);
            int col = (s >> 3) * 32 + seg * 4;
            unsigned short hx, lx, hy, ly, hz, lz, hw, lw;
            bfsplit(v.x, hx, lx); bfsplit(v.y, hy, ly);
            bfsplit(v.z, hz, lz); bfsplit(v.w, hw, lw);
            int off = ((e0 + el) * 104 + col) * 2;
            *(uint2*)(smem + X0H + off) = make_uint2(pk(hx, hy), pk(hz, hw));
            *(uint2*)(smem + X0L + off) = make_uint2(pk(lx, ly), pk(lz, lw));
        }
        __syncwarp();

        float c[8][4];

        // ================= layer 1: x0[96] @ W1 -> 64 =================
#pragma unroll
        for (int j = 0; j < 8; j++)
#pragma unroll
            for (int q = 0; q < 4; q++) c[j][q] = 0.f;
        for (int ks = 0; ks < 6; ks++) {
            int k0 = ks * 16;
            u32 aH[4], aL[4];
            u32 offA = ((e0 + arow) * 104 + k0 + asel * 8) * 2;
            ldmx4(aH, smb + X0H + offA);
            ldmx4(aL, smb + X0L + offA);
#pragma unroll
            for (int j = 0; j < 8; j++) {
                u32 offB = ((j * 8 + bn) * 104 + k0 + bsel * 8) * 2;
                u32 bH0, bH1, bL0, bL1;
                ldmx2(bH0, bH1, smb + W1H + offB);
                ldmx2(bL0, bL1, smb + W1L + offB);
                mmabf(c[j], aH, bH0, bH1);
                mmabf(c[j], aH, bL0, bL1);
                mmabf(c[j], aL, bH0, bH1);
            }
        }
        ln_epilogue(c, lnp, lnp + 64, lnp + 128, smem, H1H, H1L, e0, lane);
        __syncwarp();

        // ================= layer 2: [h1(64), x0(96)] @ W2 -> 64 =================
#pragma unroll
        for (int j = 0; j < 8; j++)
#pragma unroll
            for (int q = 0; q < 4; q++) c[j][q] = 0.f;
        for (int ks = 0; ks < 10; ks++) {
            int kb = ks * 16;
            u32 offA;
            u32 baseH, baseL;
            if (ks < 4) {
                offA = ((e0 + arow) * 72 + kb + asel * 8) * 2;
                baseH = smb + H1H; baseL = smb + H1L;
            } else {
                offA = ((e0 + arow) * 104 + (kb - 64) + asel * 8) * 2;
                baseH = smb + X0H; baseL = smb + X0L;
            }
            u32 aH[4], aL[4];
            ldmx4(aH, baseH + offA);
            ldmx4(aL, baseL + offA);
#pragma unroll
            for (int j = 0; j < 8; j++) {
                u32 offB = ((j * 8 + bn) * 168 + kb + bsel * 8) * 2;
                u32 bH0, bH1, bL0, bL1;
                ldmx2(bH0, bH1, smb + W2H + offB);
                ldmx2(bL0, bL1, smb + W2L + offB);
                mmabf(c[j], aH, bH0, bH1);
                mmabf(c[j], aH, bL0, bL1);
                mmabf(c[j], aL, bH0, bH1);
            }
        }
        ln_epilogue(c, lnp + 192, lnp + 256, lnp + 320, smem, H2H, H2L, e0, lane);
        __syncwarp();

        // ================= layer 3: h2[64] @ W3 -> 32, + b3 -> gmem =================
        {
            float c3[4][4];
#pragma unroll
            for (int j = 0; j < 4; j++)
#pragma unroll
                for (int q = 0; q < 4; q++) c3[j][q] = 0.f;
            for (int ks = 0; ks < 4; ks++) {
                int k0 = ks * 16;
                u32 aH[4], aL[4];
                u32 offA = ((e0 + arow) * 72 + k0 + asel * 8) * 2;
                ldmx4(aH, smb + H2H + offA);
                ldmx4(aL, smb + H2L + offA);
#pragma unroll
                for (int j = 0; j < 4; j++) {
                    u32 offB = ((j * 8 + bn) * 72 + k0 + bsel * 8) * 2;
                    u32 bH0, bH1, bL0, bL1;
                    ldmx2(bH0, bH1, smb + W3H + offB);
                    ldmx2(bL0, bL1, smb + W3L + offB);
                    mmabf(c3[j], aH, bH0, bH1);
                    mmabf(c3[j], aH, bL0, bL1);
                    mmabf(c3[j], aL, bH0, bH1);
                }
            }
            int geA = eb + e0 + gid, geB = geA + 8;
#pragma unroll
            for (int j = 0; j < 4; j++) {
                int col = 8 * j + 2 * tg;
                float bb0 = lnp[384 + col], bb1 = lnp[384 + col + 1];
                if (geA < E_TOTAL)
                    *(float2*)(out + (size_t)geA * 32 + col) =
                        make_float2(c3[j][0] + bb0, c3[j][1] + bb1);
                if (geB < E_TOTAL)
                    *(float2*)(out + (size_t)geB * 32 + col) =
                        make_float2(c3[j][2] + bb0, c3[j][3] + bb1);
            }
        }
        __syncwarp();
    }
}

extern "C" void kernel_launch(void* const* d_in, const int* in_sizes, int n_in,
                              void* d_out, int out_size) {
    (void)in_sizes; (void)n_in; (void)out_size;
    const float* src = (const float*)d_in[0];
    const float* dst = (const float*)d_in[1];
    const float* ea  = (const float*)d_in[2];
    const float* W1  = (const float*)d_in[3];
    const float* b1  = (const float*)d_in[4];
    const float* g1  = (const float*)d_in[5];
    const float* be1 = (const float*)d_in[6];
    const float* W2  = (const float*)d_in[7];
    const float* b2  = (const float*)d_in[8];
    const float* g2  = (const float*)d_in[9];
    const float* be2 = (const float*)d_in[10];
    const float* W3  = (const float*)d_in[11];
    const float* b3  = (const float*)d_in[12];
    float* out = (float*)d_out;

    cudaFuncSetAttribute(EdgeModel_48636209660177_kernel,
                         cudaFuncAttributeMaxDynamicSharedMemorySize, SMEM_TOTAL);
    EdgeModel_48636209660177_kernel<<<GRID, THREADS, SMEM_TOTAL>>>(
        src, dst, ea, W1, b1, g1, be1, W2, b2, g2, be2, W3, b3, out);
}

// round 11
// speedup vs baseline: 2.4761x; 1.2037x over previous
#include <cuda_runtime.h>
#include <cuda_bf16.h>

#define E_TOTAL 1000000
#define THREADS 384
#define TILE_E  192
#define NTILES  ((E_TOTAL + TILE_E - 1) / TILE_E)
#define GRID    152
#define LN_EPS  1e-5f

typedef unsigned int u32;

// ---- SMEM byte offsets (all 16B aligned) ----
// weights transposed [n][k] bf16, padded strides (halves): W1 104, W2 168, W3 72
#define W1H 0
#define W1L 13312
#define W2H 26624
#define W2L 48128
#define W3H 69632
#define W3L 74240
#define X0H 78848       // x0 [192][104] bf16
#define X0L 118784
#define HH  158720      // h  [192][72] bf16 (h1 then overwritten by h2)
#define HL  186368
#define LNP 214016      // 416 floats: b1,g1,be1,b2,g2,be2 (64 each), b3 (32)
#define SMEM_TOTAL (214016 + 416*4)

__device__ __forceinline__ u32 smem_u32(const void* p) {
    u32 a;
    asm("{ .reg .u64 t; cvta.to.shared.u64 t, %1; cvt.u32.u64 %0, t; }" : "=r"(a) : "l"(p));
    return a;
}
__device__ __forceinline__ void ldmx4(u32 r[4], u32 addr) {
    asm volatile("ldmatrix.sync.aligned.m8n8.x4.shared.b16 {%0,%1,%2,%3}, [%4];"
                 : "=r"(r[0]), "=r"(r[1]), "=r"(r[2]), "=r"(r[3]) : "r"(addr));
}
__device__ __forceinline__ void mmabf(float c[4], const u32 a[4], u32 b0, u32 b1) {
    asm volatile(
        "mma.sync.aligned.m16n8k16.row.col.f32.bf16.bf16.f32 "
        "{%0,%1,%2,%3}, {%4,%5,%6,%7}, {%8,%9}, {%0,%1,%2,%3};"
        : "+f"(c[0]), "+f"(c[1]), "+f"(c[2]), "+f"(c[3])
        : "r"(a[0]), "r"(a[1]), "r"(a[2]), "r"(a[3]), "r"(b0), "r"(b1));
}
__device__ __forceinline__ void bfsplit(float x, unsigned short &h, unsigned short &l) {
    __nv_bfloat16 hb = __float2bfloat16(x);
    float rem = x - __bfloat162float(hb);
    __nv_bfloat16 lb = __float2bfloat16(rem);
    h = __bfloat16_as_ushort(hb);
    l = __bfloat16_as_ushort(lb);
}
__device__ __forceinline__ u32 pk(unsigned short a, unsigned short b) {
    return (u32)a | ((u32)b << 16);
}

// relu -> LN(64) -> bf16 hi/lo -> h buffer (stride 72 halves). Own warp rows only.
__device__ __forceinline__ void ln_epilogue(
    float c[8][4], const float* __restrict__ lnb, const float* __restrict__ lng,
    const float* __restrict__ lnbe, char* smem, int e0, int lane)
{
    const int tg = lane & 3, gid = lane >> 2;
    float vA[16], vB[16], sA = 0.f, qA = 0.f, sB = 0.f, qB = 0.f;
#pragma unroll
    for (int j = 0; j < 8; j++) {
        int col = 8 * j + 2 * tg;
        float b0 = lnb[col], b1 = lnb[col + 1];
        float a0 = fmaxf(c[j][0] + b0, 0.f), a1 = fmaxf(c[j][1] + b1, 0.f);
        float d0 = fmaxf(c[j][2] + b0, 0.f), d1 = fmaxf(c[j][3] + b1, 0.f);
        vA[2 * j] = a0; vA[2 * j + 1] = a1;
        vB[2 * j] = d0; vB[2 * j + 1] = d1;
        sA += a0 + a1; qA += a0 * a0 + a1 * a1;
        sB += d0 + d1; qB += d0 * d0 + d1 * d1;
    }
#pragma unroll
    for (int m = 1; m < 4; m <<= 1) {
        sA += __shfl_xor_sync(0xffffffffu, sA, m);
        qA += __shfl_xor_sync(0xffffffffu, qA, m);
        sB += __shfl_xor_sync(0xffffffffu, sB, m);
        qB += __shfl_xor_sync(0xffffffffu, qB, m);
    }
    float mA = sA * (1.f / 64.f), mB = sB * (1.f / 64.f);
    float rA = rsqrtf(qA * (1.f / 64.f) - mA * mA + LN_EPS);
    float rB = rsqrtf(qB * (1.f / 64.f) - mB * mB + LN_EPS);
    const int rowA = e0 + gid, rowB = rowA + 8;
#pragma unroll
    for (int j = 0; j < 8; j++) {
        int col = 8 * j + 2 * tg;
        float g0 = lng[col], g1v = lng[col + 1];
        float p0 = lnbe[col], p1 = lnbe[col + 1];
        float yA0 = (vA[2 * j] - mA) * rA * g0 + p0;
        float yA1 = (vA[2 * j + 1] - mA) * rA * g1v + p1;
        float yB0 = (vB[2 * j] - mB) * rB * g0 + p0;
        float yB1 = (vB[2 * j + 1] - mB) * rB * g1v + p1;
        unsigned short h0, l0, h1, l1;
        bfsplit(yA0, h0, l0); bfsplit(yA1, h1, l1);
        *(u32*)(smem + HH + (rowA * 72 + col) * 2) = pk(h0, h1);
        *(u32*)(smem + HL + (rowA * 72 + col) * 2) = pk(l0, l1);
        bfsplit(yB0, h0, l0); bfsplit(yB1, h1, l1);
        *(u32*)(smem + HH + (rowB * 72 + col) * 2) = pk(h0, h1);
        *(u32*)(smem + HL + (rowB * 72 + col) * 2) = pk(l0, l1);
    }
}

__global__ __launch_bounds__(THREADS, 1)
void EdgeModel_48636209660177_kernel(
    const float* __restrict__ src, const float* __restrict__ dst,
    const float* __restrict__ ea,
    const float* __restrict__ W1, const float* __restrict__ b1,
    const float* __restrict__ g1, const float* __restrict__ be1,
    const float* __restrict__ W2, const float* __restrict__ b2,
    const float* __restrict__ g2, const float* __restrict__ be2,
    const float* __restrict__ W3, const float* __restrict__ b3,
    float* __restrict__ out)
{
    extern __shared__ char smem[];
    const u32 smb = smem_u32(smem);
    const int tid = threadIdx.x, lane = tid & 31, warp = tid >> 5;
    float* lnp = (float*)(smem + LNP);

    // ---- one-time: weights -> transposed bf16 hi/lo; LN params -> smem ----
    for (int i = tid; i < 96 * 64; i += THREADS) {
        int k = i >> 6, n = i & 63;
        unsigned short h, l; bfsplit(__ldg(&W1[i]), h, l);
        int off = (n * 104 + k) * 2;
        *(unsigned short*)(smem + W1H + off) = h;
        *(unsigned short*)(smem + W1L + off) = l;
    }
    for (int i = tid; i < 160 * 64; i += THREADS) {
        int k = i >> 6, n = i & 63;
        unsigned short h, l; bfsplit(__ldg(&W2[i]), h, l);
        int off = (n * 168 + k) * 2;
        *(unsigned short*)(smem + W2H + off) = h;
        *(unsigned short*)(smem + W2L + off) = l;
    }
    for (int i = tid; i < 64 * 32; i += THREADS) {
        int k = i >> 5, n = i & 31;
        unsigned short h, l; bfsplit(__ldg(&W3[i]), h, l);
        int off = (n * 72 + k) * 2;
        *(unsigned short*)(smem + W3H + off) = h;
        *(unsigned short*)(smem + W3L + off) = l;
    }
    for (int i = tid; i < 64; i += THREADS) {
        lnp[i] = b1[i]; lnp[64 + i] = g1[i]; lnp[128 + i] = be1[i];
        lnp[192 + i] = b2[i]; lnp[256 + i] = g2[i]; lnp[320 + i] = be2[i];
    }
    for (int i = tid; i < 32; i += THREADS) lnp[384 + i] = b3[i];
    __syncthreads();

    const int e0 = warp * 16;                 // this warp's 16 edge rows (fixed)
    const int tg = lane & 3, gid = lane >> 2;
    // A ldmatrix lane addressing: row within 16, k-half select
    const int arow = lane & 15, asel = lane >> 4;
    // B pair-x4 lane addressing: lanes 0-15 -> column jp, 16-31 -> jp+1
    const int brow = ((lane >> 4) << 3) + (lane & 7);   // (lane>=16 ? 8 : 0) + n-row
    const int boff = ((lane >> 3) & 1) * 16;            // k-half byte offset

    for (int tile = blockIdx.x; tile < NTILES; tile += GRID) {
        const int eb = tile * TILE_E;

        // ---- stage own 16 edges of x0 (bf16 hi/lo, [e][k] stride 104) ----
        for (int i = lane; i < 16 * 24; i += 32) {
            int el = i / 24, s = i % 24;
            int ge = eb + e0 + el;
            const float* g = (s < 8) ? src : (s < 16) ? dst : ea;
            int seg = s & 7;
            float4 v = make_float4(0.f, 0.f, 0.f, 0.f);
            if (ge < E_TOTAL) v = *(const float4*)(g + (size_t)ge * 32 + seg * 4);
            int col = (s >> 3) * 32 + seg * 4;
            unsigned short hx, lx, hy, ly, hz, lz, hw, lw;
            bfsplit(v.x, hx, lx); bfsplit(v.y, hy, ly);
            bfsplit(v.z, hz, lz); bfsplit(v.w, hw, lw);
            int off = ((e0 + el) * 104 + col) * 2;
            *(uint2*)(smem + X0H + off) = make_uint2(pk(hx, hy), pk(hz, hw));
            *(uint2*)(smem + X0L + off) = make_uint2(pk(lx, ly), pk(lz, lw));
        }
        __syncwarp();

        float c[8][4];

        // ================= layer 1: x0[96] @ W1 -> 64 =================
#pragma unroll
        for (int j = 0; j < 8; j++)
#pragma unroll
            for (int q = 0; q < 4; q++) c[j][q] = 0.f;
#pragma unroll
        for (int ks = 0; ks < 6; ks++) {
            int k0 = ks * 16;
            u32 aH[4], aL[4];
            u32 offA = ((e0 + arow) * 104 + k0 + asel * 8) * 2;
            ldmx4(aH, smb + X0H + offA);
            ldmx4(aL, smb + X0L + offA);
#pragma unroll
            for (int jp = 0; jp < 8; jp += 2) {
                u32 addr = ((jp * 8 + brow) * 104 + k0) * 2 + boff;
                u32 bH[4], bL[4];
                ldmx4(bH, smb + W1H + addr);
                ldmx4(bL, smb + W1L + addr);
                mmabf(c[jp], aH, bH[0], bH[1]);
                mmabf(c[jp], aH, bL[0], bL[1]);
                mmabf(c[jp], aL, bH[0], bH[1]);
                mmabf(c[jp + 1], aH, bH[2], bH[3]);
                mmabf(c[jp + 1], aH, bL[2], bL[3]);
                mmabf(c[jp + 1], aL, bH[2], bH[3]);
            }
        }
        ln_epilogue(c, lnp, lnp + 64, lnp + 128, smem, e0, lane);
        __syncwarp();

        // ================= layer 2: [h1(64), x0(96)] @ W2 -> 64 =================
#pragma unroll
        for (int j = 0; j < 8; j++)
#pragma unroll
            for (int q = 0; q < 4; q++) c[j][q] = 0.f;
#pragma unroll
        for (int ks = 0; ks < 10; ks++) {
            int kb = ks * 16;
            u32 offA, baseH, baseL;
            if (ks < 4) {
                offA = ((e0 + arow) * 72 + kb + asel * 8) * 2;
                baseH = smb + HH; baseL = smb + HL;
            } else {
                offA = ((e0 + arow) * 104 + (kb - 64) + asel * 8) * 2;
                baseH = smb + X0H; baseL = smb + X0L;
            }
            u32 aH[4], aL[4];
            ldmx4(aH, baseH + offA);
            ldmx4(aL, baseL + offA);
#pragma unroll
            for (int jp = 0; jp < 8; jp += 2) {
                u32 addr = ((jp * 8 + brow) * 168 + kb) * 2 + boff;
                u32 bH[4], bL[4];
                ldmx4(bH, smb + W2H + addr);
                ldmx4(bL, smb + W2L + addr);
                mmabf(c[jp], aH, bH[0], bH[1]);
                mmabf(c[jp], aH, bL[0], bL[1]);
                mmabf(c[jp], aL, bH[0], bH[1]);
                mmabf(c[jp + 1], aH, bH[2], bH[3]);
                mmabf(c[jp + 1], aH, bL[2], bL[3]);
                mmabf(c[jp + 1], aL, bH[2], bH[3]);
            }
        }
        ln_epilogue(c, lnp + 192, lnp + 256, lnp + 320, smem, e0, lane);
        __syncwarp();

        // ================= layer 3: h2[64] @ W3 -> 32, + b3 -> gmem =================
        {
            float c3[4][4];
#pragma unroll
            for (int j = 0; j < 4; j++)
#pragma unroll
                for (int q = 0; q < 4; q++) c3[j][q] = 0.f;
#pragma unroll
            for (int ks = 0; ks < 4; ks++) {
                int k0 = ks * 16;
                u32 aH[4], aL[4];
                u32 offA = ((e0 + arow) * 72 + k0 + asel * 8) * 2;
                ldmx4(aH, smb + HH + offA);
                ldmx4(aL, smb + HL + offA);
#pragma unroll
                for (int jp = 0; jp < 4; jp += 2) {
                    u32 addr = ((jp * 8 + brow) * 72 + k0) * 2 + boff;
                    u32 bH[4], bL[4];
                    ldmx4(bH, smb + W3H + addr);
                    ldmx4(bL, smb + W3L + addr);
                    mmabf(c3[jp], aH, bH[0], bH[1]);
                    mmabf(c3[jp], aH, bL[0], bL[1]);
                    mmabf(c3[jp], aL, bH[0], bH[1]);
                    mmabf(c3[jp + 1], aH, bH[2], bH[3]);
                    mmabf(c3[jp + 1], aH, bL[2], bL[3]);
                    mmabf(c3[jp + 1], aL, bH[2], bH[3]);
                }
            }
            int geA = eb + e0 + gid, geB = geA + 8;
#pragma unroll
            for (int j = 0; j < 4; j++) {
                int col = 8 * j + 2 * tg;
                float bb0 = lnp[384 + col], bb1 = lnp[384 + col + 1];
                if (geA < E_TOTAL)
                    *(float2*)(out + (size_t)geA * 32 + col) =
                        make_float2(c3[j][0] + bb0, c3[j][1] + bb1);
                if (geB < E_TOTAL)
                    *(float2*)(out + (size_t)geB * 32 + col) =
                        make_float2(c3[j][2] + bb0, c3[j][3] + bb1);
            }
        }
        __syncwarp();
    }
}

extern "C" void kernel_launch(void* const* d_in, const int* in_sizes, int n_in,
                              void* d_out, int out_size) {
    (void)in_sizes; (void)n_in; (void)out_size;
    const float* src = (const float*)d_in[0];
    const float* dst = (const float*)d_in[1];
    const float* ea  = (const float*)d_in[2];
    const float* W1  = (const float*)d_in[3];
    const float* b1  = (const float*)d_in[4];
    const float* g1  = (const float*)d_in[5];
    const float* be1 = (const float*)d_in[6];
    const float* W2  = (const float*)d_in[7];
    const float* b2  = (const float*)d_in[8];
    const float* g2  = (const float*)d_in[9];
    const float* be2 = (const float*)d_in[10];
    const float* W3  = (const float*)d_in[11];
    const float* b3  = (const float*)d_in[12];
    float* out = (float*)d_out;

    cudaFuncSetAttribute(EdgeModel_48636209660177_kernel,
                         cudaFuncAttributeMaxDynamicSharedMemorySize, SMEM_TOTAL);
    EdgeModel_48636209660177_kernel<<<GRID, THREADS, SMEM_TOTAL>>>(
        src, dst, ea, W1, b1, g1, be1, W2, b2, g2, be2, W3, b3, out);
}